// round 15
// baseline (speedup 1.0000x reference)
#include <cuda_runtime.h>
#include <cuda_bf16.h>
#include <math.h>
#include <stdint.h>

#define TPB 256

namespace {

constexpr int B_ = 4, N_ = 1024, D_ = 512, H_ = 8, DH_ = 64, BH_ = 32, KHOP = 3;
constexpr int NCHUNK = 2, BH_PER_CHUNK = BH_ / NCHUNK;   // 16 bh per chunk (wide)

using u64 = unsigned long long;

// Device-global scratch (no allocations allowed)
__device__ float g_S[(size_t)BH_ * N_ * N_];                 // 128 MB fp32 scaled scores
__device__ __nv_bfloat16 g_Ahi[(size_t)BH_ * N_ * N_];       // 64 MB adjacency hi
__device__ __nv_bfloat16 g_Alo[(size_t)BH_ * N_ * N_];       // 64 MB adjacency lo
__device__ __nv_bfloat16 g_Xhi[(size_t)BH_ * N_ * DH_];      // 4 MB  Xh hi (k-major)
__device__ __nv_bfloat16 g_Xlo[(size_t)BH_ * N_ * DH_];      // 4 MB  Xh lo
// Ping-pong P^T buffers: reader and writer of a given spmm launch are disjoint.
__device__ __nv_bfloat16 g_PThi[2][(size_t)BH_ * DH_ * N_];  // 2 x 4 MB
__device__ __nv_bfloat16 g_PTlo[2][(size_t)BH_ * DH_ * N_];  // 2 x 4 MB
__device__ float g_P[KHOP + 1][(size_t)BH_ * N_ * DH_];      // 4 x 8 MB hop buffers
__device__ __nv_bfloat16 g_Hhi[(size_t)B_ * N_ * D_];        // 4 MB filtered out hi
__device__ __nv_bfloat16 g_Hlo[(size_t)B_ * N_ * D_];        // 4 MB filtered out lo
__device__ __nv_bfloat16 g_Wphi[(size_t)D_ * D_];            // 0.5 MB W_proj hi
__device__ __nv_bfloat16 g_Wplo[(size_t)D_ * D_];            // 0.5 MB W_proj lo

// ---------------------------------------------------------------------------
// Packed f32x2 helpers (SIMT filter kernel)
// ---------------------------------------------------------------------------
__device__ __forceinline__ u64 ffma2(u64 a, u64 b, u64 c) {
    u64 d;
    asm("fma.rn.f32x2 %0, %1, %2, %3;" : "=l"(d) : "l"(a), "l"(b), "l"(c));
    return d;
}
__device__ __forceinline__ u64 dup2(float s) {
    u64 d;
    asm("mov.b64 %0, {%1, %1};" : "=l"(d) : "f"(s));
    return d;
}
__device__ __forceinline__ float2 unpack2(u64 v) {
    float2 r;
    asm("mov.b64 {%0, %1}, %2;" : "=f"(r.x), "=f"(r.y) : "l"(v));
    return r;
}

// ---------------------------------------------------------------------------
// cp.async + ldmatrix + mma.sync helpers (valid on compute_103)
// ---------------------------------------------------------------------------
__device__ __forceinline__ uint32_t smem_u32(const void* p) {
    return (uint32_t)__cvta_generic_to_shared(p);
}
__device__ __forceinline__ void cp16(uint32_t s, const void* g) {
    asm volatile("cp.async.cg.shared.global [%0], [%1], 16;" :: "r"(s), "l"(g));
}
#define CP_COMMIT() asm volatile("cp.async.commit_group;" ::: "memory")
#define CP_WAIT1()  asm volatile("cp.async.wait_group 1;" ::: "memory")
#define CP_WAIT0()  asm volatile("cp.async.wait_group 0;" ::: "memory")

__device__ __forceinline__ void ldsm4(uint32_t r[4], uint32_t addr) {
    asm volatile("ldmatrix.sync.aligned.m8n8.x4.shared.b16 {%0,%1,%2,%3}, [%4];"
                 : "=r"(r[0]), "=r"(r[1]), "=r"(r[2]), "=r"(r[3]) : "r"(addr));
}
__device__ __forceinline__ void mma16816(float d[4], const uint32_t a[4],
                                         uint32_t b0, uint32_t b1) {
    asm volatile(
        "mma.sync.aligned.m16n8k16.row.col.f32.bf16.bf16.f32 "
        "{%0,%1,%2,%3}, {%4,%5,%6,%7}, {%8,%9}, {%0,%1,%2,%3};"
        : "+f"(d[0]), "+f"(d[1]), "+f"(d[2]), "+f"(d[3])
        : "r"(a[0]), "r"(a[1]), "r"(a[2]), "r"(a[3]), "r"(b0), "r"(b1));
}

__device__ __forceinline__ void split_bf16(float v, __nv_bfloat16& h, __nv_bfloat16& l) {
    h = __float2bfloat16(v);
    l = __float2bfloat16(v - __bfloat162float(h));
}

__device__ __forceinline__ uint32_t pack_split2(float v0, float v1, uint32_t& lo2) {
    uint32_t hi2;
    asm("cvt.rn.bf16x2.f32 %0, %1, %2;" : "=r"(hi2) : "f"(v1), "f"(v0));
    float h0 = __uint_as_float(hi2 << 16);
    float h1 = __uint_as_float(hi2 & 0xFFFF0000u);
    float l0 = v0 - h0, l1 = v1 - h1;
    asm("cvt.rn.bf16x2.f32 %0, %1, %2;" : "=r"(lo2) : "f"(l1), "f"(l0));
    return hi2;
}

// SMEM layout for mma GEMM kernels: 2 stages x 32KB
constexpr int OFF_AHI = 0;
constexpr int OFF_ALO = 8192;
constexpr int OFF_PHI = 16384;
constexpr int OFF_PLO = 24576;
constexpr int STAGE_BYTES = 32768;
constexpr int SMEM_SPMM = 2 * STAGE_BYTES;   // 64 KB dynamic

// ---------------------------------------------------------------------------
// Tile I/O for SIMT kernels
// ---------------------------------------------------------------------------
__device__ __forceinline__ void ldg_tile(float4 r[4], const float* g, int ldg) {
    int t = threadIdx.x;
#pragma unroll
    for (int i = 0; i < 4; i++) {
        int idx = t + i * TPB;
        int rr = idx >> 4, k4 = idx & 15;
        r[i] = *(const float4*)(g + (size_t)rr * ldg + (k4 << 2));
    }
}
__device__ __forceinline__ void sts_tile(float4* s, const float4 r[4]) {
    int t = threadIdx.x;
#pragma unroll
    for (int i = 0; i < 4; i++) {
        int idx = t + i * TPB;
        int rr = idx >> 4, k4 = idx & 15;
        s[rr * 16 + (k4 ^ (rr >> 2))] = r[i];
    }
}
__device__ __forceinline__ float getc(const float4& v, int c) {
    return c == 0 ? v.x : c == 1 ? v.y : c == 2 ? v.z : v.w;
}

// ---------------------------------------------------------------------------
// Pack Xh: fp32 P[0] + bf16 hi/lo Xh
// ---------------------------------------------------------------------------
__global__ __launch_bounds__(TPB) void pack_kernel(const float* __restrict__ X) {
    int idx = blockIdx.x * TPB + threadIdx.x;
    int d4 = idx & 15;
    int n  = (idx >> 4) & (N_ - 1);
    int bh = idx >> 14;
    int b = bh >> 3, h = bh & 7;
    float4 v = *(const float4*)(X + ((size_t)b * N_ + n) * D_ + h * DH_ + (d4 << 2));
    size_t off = ((size_t)bh * N_ + n) * DH_ + (d4 << 2);
    *(float4*)(&g_P[0][off]) = v;

    uint32_t l01, l23;
    uint32_t h01 = pack_split2(v.x, v.y, l01);
    uint32_t h23 = pack_split2(v.z, v.w, l23);
    *(uint2*)(g_Xhi + off) = make_uint2(h01, h23);
    *(uint2*)(g_Xlo + off) = make_uint2(l01, l23);
}

// ---------------------------------------------------------------------------
// W_proj fp32 [j][d] (k-major) -> bf16 hi/lo
// ---------------------------------------------------------------------------
__global__ __launch_bounds__(TPB) void wp_convert_kernel(const float* __restrict__ Wp) {
    int idx = blockIdx.x * TPB + threadIdx.x;       // 65536 float4 groups
    float4 v = ((const float4*)Wp)[idx];
    uint32_t l01, l23;
    uint32_t h01 = pack_split2(v.x, v.y, l01);
    uint32_t h23 = pack_split2(v.z, v.w, l23);
    *(uint2*)(g_Wphi + (size_t)idx * 4) = make_uint2(h01, h23);
    *(uint2*)(g_Wplo + (size_t)idx * 4) = make_uint2(l01, l23);
}

// ---------------------------------------------------------------------------
// Score via mma.sync bf16x3: S = Xh Xh^T / (8*clip(tau)); 64x64 CTA, K=64.
// ---------------------------------------------------------------------------
__global__ __launch_bounds__(128) void score_mma_kernel(const float* __restrict__ temp,
                                                        int bh0) {
    __shared__ __align__(128) char sa_hi[8192], sa_lo[8192], sb_hi[8192], sb_lo[8192];
    int tid = threadIdx.x, lane = tid & 31, w = tid >> 5;
    int mt = blockIdx.y << 6, nt = blockIdx.x << 6;
    int bh = bh0 + blockIdx.z, h = bh & 7;

    const __nv_bfloat16* Xhi = g_Xhi + (size_t)bh * N_ * DH_;
    const __nv_bfloat16* Xlo = g_Xlo + (size_t)bh * N_ * DH_;

    {
        uint32_t ah = smem_u32(sa_hi), al = smem_u32(sa_lo);
        uint32_t bhp = smem_u32(sb_hi), blp = smem_u32(sb_lo);
#pragma unroll
        for (int i = 0; i < 4; i++) {
            int idx = tid + i * 128;
            int r = idx >> 3, g = idx & 7;
            uint32_t so = (uint32_t)(r * 128 + ((g ^ (r & 7)) << 4));
            size_t ga = ((size_t)(mt + r) * DH_ + g * 8) * 2;
            size_t gb = ((size_t)(nt + r) * DH_ + g * 8) * 2;
            cp16(ah + so, (const char*)Xhi + ga);
            cp16(al + so, (const char*)Xlo + ga);
            cp16(bhp + so, (const char*)Xhi + gb);
            cp16(blp + so, (const char*)Xlo + gb);
        }
    }
    CP_COMMIT();
    CP_WAIT0();
    __syncthreads();

    int lr = lane & 7, sel = lane >> 3;
    int amrow = (w << 4) + ((sel & 1) << 3) + lr;
    uint32_t aRowOff = (uint32_t)(amrow * 128);
    int aRowX = amrow & 7;
    int aCsel = sel >> 1;
    int bnrow = ((sel >> 1) << 3) + lr;
    int bCsel = sel & 1;

    float acc[8][4];
#pragma unroll
    for (int j = 0; j < 8; j++)
#pragma unroll
        for (int q = 0; q < 4; q++) acc[j][q] = 0.f;

    uint32_t sah = smem_u32(sa_hi), sal = smem_u32(sa_lo);
    uint32_t sbh = smem_u32(sb_hi), sbl = smem_u32(sb_lo);
#pragma unroll
    for (int ks = 0; ks < 4; ks++) {
        uint32_t ahi[4], alo[4];
        {
            int c = 2 * ks + aCsel;
            uint32_t ao = aRowOff + (uint32_t)((c ^ aRowX) << 4);
            ldsm4(ahi, sah + ao);
            ldsm4(alo, sal + ao);
        }
#pragma unroll
        for (int p = 0; p < 4; p++) {
            int n = (p << 4) + bnrow;
            int c = 2 * ks + bCsel;
            uint32_t bo = (uint32_t)(n * 128 + ((c ^ (n & 7)) << 4));
            uint32_t bhi[4], blo[4];
            ldsm4(bhi, sbh + bo);
            ldsm4(blo, sbl + bo);
            mma16816(acc[2 * p],     ahi, bhi[0], bhi[1]);
            mma16816(acc[2 * p],     ahi, blo[0], blo[1]);
            mma16816(acc[2 * p],     alo, bhi[0], bhi[1]);
            mma16816(acc[2 * p + 1], ahi, bhi[2], bhi[3]);
            mma16816(acc[2 * p + 1], ahi, blo[2], blo[3]);
            mma16816(acc[2 * p + 1], alo, bhi[2], bhi[3]);
        }
    }

    float tau = fminf(fmaxf(temp[h], 0.1f), 5.0f);
    float sc = 1.0f / (8.0f * tau);

    float* Sb = g_S + (size_t)bh * N_ * N_;
    int r0 = mt + (w << 4) + (lane >> 2);
    int cc = nt + ((lane & 3) << 1);
#pragma unroll
    for (int j = 0; j < 8; j++) {
        *(float2*)(Sb + (size_t)r0 * N_ + j * 8 + cc) =
            make_float2(acc[j][0] * sc, acc[j][1] * sc);
        *(float2*)(Sb + (size_t)(r0 + 8) * N_ + j * 8 + cc) =
            make_float2(acc[j][2] * sc, acc[j][3] * sc);
    }
}

// ---------------------------------------------------------------------------
// Exact top-k threshold + softmax, warp-per-row; emits bf16 hi/lo adjacency.
// Register diet: only uu[32] kept live. Phase-1 compares full keys against
// cand<<16 (equivalent to hi16 compare); floats reconstructed exactly from
// keys at softmax time; uu reused for exp values. Output bit-identical.
// ---------------------------------------------------------------------------
__global__ __launch_bounds__(TPB) void topk_softmax_kernel(const int* __restrict__ layer_idx,
                                                           const int* __restrict__ Lp,
                                                           int row0) {
    int lane = threadIdx.x & 31;
    size_t row = (size_t)row0 + (size_t)blockIdx.x * (TPB / 32) + (threadIdx.x >> 5);
    const float4* s4 = (const float4*)(g_S + row * N_);

    unsigned uu[32];
#pragma unroll
    for (int i = 0; i < 8; i++) {
        float4 x = s4[lane + i * 32];
        const float* f = (const float*)&x;
#pragma unroll
        for (int j = 0; j < 4; j++) {
            unsigned bits = __float_as_uint(f[j]);
            uu[i * 4 + j] = (bits & 0x80000000u) ? ~bits : (bits | 0x80000000u);
        }
    }

    int li = layer_idx[0], Lv = Lp[0];
    double sp = 0.8 + (0.2 - 0.8) * exp(-3.0 * (double)li / (double)Lv);
    int k_val = (int)((1.0 - sp) * (double)N_);
    if (k_val < 1) k_val = 1;
    bool do_thresh = (k_val < N_);

    unsigned T = 0u;
    if (do_thresh) {
        // Phase 1: binary search the high 16 bits, comparing full keys.
        unsigned P16 = 0u;   // threshold with low 16 bits zero
        bool exact = false;
#pragma unroll 1
        for (int b = 31; b >= 16; --b) {
            unsigned cand = P16 | (1u << b);
            int c = 0;
#pragma unroll
            for (int i = 0; i < 32; i++) c += (uu[i] >= cand) ? 1 : 0;
            c = __reduce_add_sync(0xFFFFFFFFu, c);
            if (c >= k_val) {
                P16 = cand;
                if (c == k_val) { exact = true; break; }
            }
        }

        if (exact) {
            T = P16;
        } else {
            int cgt = 0;
            unsigned hibound = P16 + 0x10000u;   // keys with hi > P16
#pragma unroll
            for (int i = 0; i < 32; i++) cgt += (uu[i] >= hibound) ? 1 : 0;
            cgt = __reduce_add_sync(0xFFFFFFFFu, cgt);
            int j = k_val - cgt;

            unsigned act = 0u;
#pragma unroll
            for (int i = 0; i < 32; i++)
                if ((uu[i] & 0xFFFF0000u) == P16) act |= (1u << i);

            unsigned Mfin = 0u;
#pragma unroll 1
            while (true) {
                unsigned m = 0u;
#pragma unroll
                for (int i = 0; i < 32; i++)
                    if (act & (1u << i)) {
                        unsigned lo = uu[i] & 0xFFFFu;
                        m = m > lo ? m : lo;
                    }
                m = __reduce_max_sync(0xFFFFFFFFu, m);
                int q = 0;
                unsigned hitm = 0u;
#pragma unroll
                for (int i = 0; i < 32; i++)
                    if ((act & (1u << i)) && (uu[i] & 0xFFFFu) == m) {
                        q++;
                        hitm |= (1u << i);
                    }
                q = __reduce_add_sync(0xFFFFFFFFu, q);
                if (j <= q) { Mfin = m; break; }
                j -= q;
                act &= ~hitm;
            }
            T = P16 | Mfin;
        }
    }

    // Row max in key domain (order-isomorphic), reconstruct once.
    unsigned umax = 0u;
#pragma unroll
    for (int i = 0; i < 32; i++) umax = umax > uu[i] ? umax : uu[i];
    umax = __reduce_max_sync(0xFFFFFFFFu, umax);
    unsigned mb = (umax & 0x80000000u) ? (umax ^ 0x80000000u) : ~umax;
    float vmax = __uint_as_float(mb);

    float ssum = 0.f;
#pragma unroll
    for (int i = 0; i < 32; i++) {
        unsigned u = uu[i];
        bool keep = (!do_thresh) || (u >= T);
        unsigned bits = (u & 0x80000000u) ? (u ^ 0x80000000u) : ~u;
        float ev = keep ? expf(__uint_as_float(bits) - vmax) : 0.f;
        uu[i] = __float_as_uint(ev);     // reuse key registers for exp values
        ssum += ev;
    }
#pragma unroll
    for (int o = 16; o > 0; o >>= 1)
        ssum += __shfl_xor_sync(0xFFFFFFFFu, ssum, o);
    float inv = 1.0f / ssum;

    __nv_bfloat16* ahrow = g_Ahi + row * N_;
    __nv_bfloat16* alrow = g_Alo + row * N_;
#pragma unroll
    for (int i = 0; i < 8; i++) {
        __nv_bfloat16 hh[4], ll[4];
#pragma unroll
        for (int j = 0; j < 4; j++)
            split_bf16(__uint_as_float(uu[i * 4 + j]) * inv, hh[j], ll[j]);
        *(uint2*)(ahrow + (lane + i * 32) * 4) = *(const uint2*)hh;
        *(uint2*)(alrow + (lane + i * 32) * 4) = *(const uint2*)ll;
    }
}

// ---------------------------------------------------------------------------
// PT convert (hop 0 only): P[0] fp32 -> PT buffer 0 bf16 hi/lo [bh][n][k]
// ---------------------------------------------------------------------------
__global__ __launch_bounds__(128) void pt_convert_kernel(int hop) {
    __shared__ float tile[64][65];
    int kt = blockIdx.x, bh = blockIdx.y;
    const float* src = &g_P[hop][(size_t)bh * N_ * DH_ + (size_t)kt * 64 * DH_];
    int t = threadIdx.x;
#pragma unroll
    for (int i = 0; i < 8; i++) {
        int idx = t + i * 128;
        int r = idx >> 4, c4 = idx & 15;
        float4 v = *(const float4*)(src + (size_t)r * DH_ + c4 * 4);
        tile[r][c4 * 4 + 0] = v.x;
        tile[r][c4 * 4 + 1] = v.y;
        tile[r][c4 * 4 + 2] = v.z;
        tile[r][c4 * 4 + 3] = v.w;
    }
    __syncthreads();
    int n = t >> 1, kh = (t & 1) * 32;
    __nv_bfloat16 hi[32], lo[32];
#pragma unroll
    for (int k = 0; k < 32; k++) split_bf16(tile[kh + k][n], hi[k], lo[k]);
    size_t off = ((size_t)bh * DH_ + n) * N_ + kt * 64 + kh;
#pragma unroll
    for (int q = 0; q < 4; q++) {
        *(uint4*)(&g_PThi[0][off + q * 8]) = *(const uint4*)(hi + q * 8);
        *(uint4*)(&g_PTlo[0][off + q * 8]) = *(const uint4*)(lo + q * 8);
    }
}

// ---------------------------------------------------------------------------
// spmm via mma.sync bf16x3:  P[hop] = A @ P[hop-1].
// Reads PT[rb], optionally writes transposed PT[wb] (rb != wb: race-free).
// ---------------------------------------------------------------------------
__device__ __forceinline__ void spmm_load_chunk(
    uint32_t st, const __nv_bfloat16* Ahi, const __nv_bfloat16* Alo,
    const __nv_bfloat16* Phi, const __nv_bfloat16* Plo, int mt, int k0)
{
    int t = threadIdx.x;
#pragma unroll
    for (int i = 0; i < 4; i++) {
        int idx = t + i * 128;
        int r = idx >> 3, g = idx & 7;
        uint32_t so = (uint32_t)(r * 128 + ((g ^ (r & 7)) << 4));
        size_t go = ((size_t)(mt + r) * N_ + k0 + g * 8) * 2;
        cp16(st + OFF_AHI + so, (const char*)Ahi + go);
        cp16(st + OFF_ALO + so, (const char*)Alo + go);
        size_t gp = ((size_t)r * N_ + k0 + g * 8) * 2;
        cp16(st + OFF_PHI + so, (const char*)Phi + gp);
        cp16(st + OFF_PLO + so, (const char*)Plo + gp);
    }
}

constexpr int TSTRIDE = 72;   // bf16 elements; pads banks for transposed readout

__global__ __launch_bounds__(128, 3) void spmm_mma_kernel(int hop, int want_pt,
                                                          int bh0, int rb, int wb) {
    extern __shared__ __align__(1024) char dsm[];
    uint32_t sb = smem_u32(dsm);
    int tid = threadIdx.x, lane = tid & 31, w = tid >> 5;
    int mt = blockIdx.x << 6;
    int bh = bh0 + blockIdx.y;

    const __nv_bfloat16* Ahi = g_Ahi + (size_t)bh * N_ * N_;
    const __nv_bfloat16* Alo = g_Alo + (size_t)bh * N_ * N_;
    const __nv_bfloat16* Phi = &g_PThi[rb][(size_t)bh * DH_ * N_];
    const __nv_bfloat16* Plo = &g_PTlo[rb][(size_t)bh * DH_ * N_];
    float* Pout = &g_P[hop][(size_t)bh * N_ * DH_];

    int lr = lane & 7, sel = lane >> 3;
    int amrow = (w << 4) + ((sel & 1) << 3) + lr;
    uint32_t aRowOff = (uint32_t)(amrow * 128);
    int aRowX = amrow & 7;
    int aCsel = sel >> 1;
    int bnrow = ((sel >> 1) << 3) + lr;
    int bCsel = sel & 1;

    float acc[8][4];
#pragma unroll
    for (int j = 0; j < 8; j++)
#pragma unroll
        for (int q = 0; q < 4; q++) acc[j][q] = 0.f;

    spmm_load_chunk(sb, Ahi, Alo, Phi, Plo, mt, 0);
    CP_COMMIT();

#pragma unroll 1
    for (int kc = 0; kc < 16; kc++) {
        uint32_t cur = (uint32_t)(kc & 1) * STAGE_BYTES;
        if (kc < 15) {
            uint32_t nxt = (uint32_t)((kc + 1) & 1) * STAGE_BYTES;
            spmm_load_chunk(sb + nxt, Ahi, Alo, Phi, Plo, mt, (kc + 1) * 64);
            CP_COMMIT();
            CP_WAIT1();
        } else {
            CP_WAIT0();
        }
        __syncthreads();

#pragma unroll
        for (int ks = 0; ks < 4; ks++) {
            uint32_t ahi[4], alo[4];
            {
                int c = 2 * ks + aCsel;
                uint32_t ao = aRowOff + (uint32_t)((c ^ aRowX) << 4);
                ldsm4(ahi, sb + cur + OFF_AHI + ao);
                ldsm4(alo, sb + cur + OFF_ALO + ao);
            }
#pragma unroll
            for (int p = 0; p < 4; p++) {
                int n = (p << 4) + bnrow;
                int c = 2 * ks + bCsel;
                uint32_t bo = (uint32_t)(n * 128 + ((c ^ (n & 7)) << 4));
                uint32_t bhi[4], blo[4];
                ldsm4(bhi, sb + cur + OFF_PHI + bo);
                ldsm4(blo, sb + cur + OFF_PLO + bo);
                mma16816(acc[2 * p],     ahi, bhi[0], bhi[1]);
                mma16816(acc[2 * p],     ahi, blo[0], blo[1]);
                mma16816(acc[2 * p],     alo, bhi[0], bhi[1]);
                mma16816(acc[2 * p + 1], ahi, bhi[2], bhi[3]);
                mma16816(acc[2 * p + 1], ahi, blo[2], blo[3]);
                mma16816(acc[2 * p + 1], alo, bhi[2], bhi[3]);
            }
        }
        __syncthreads();
    }

    // fp32 P output
    int lrow = (w << 4) + (lane >> 2);       // local row 0..63
    int r0 = mt + lrow;
    int cc = (lane & 3) << 1;
#pragma unroll
    for (int j = 0; j < 8; j++) {
        *(float2*)(Pout + (size_t)r0 * DH_ + j * 8 + cc) =
            make_float2(acc[j][0], acc[j][1]);
        *(float2*)(Pout + (size_t)(r0 + 8) * DH_ + j * 8 + cc) =
            make_float2(acc[j][2], acc[j][3]);
    }

    // Fused transposed bf16 hi/lo PT output into the OTHER buffer (wb != rb)
    if (want_pt) {
        __nv_bfloat16* Thi = (__nv_bfloat16*)dsm;
        __nv_bfloat16* Tlo = (__nv_bfloat16*)(dsm + 64 * TSTRIDE * 2);
#pragma unroll
        for (int j = 0; j < 8; j++) {
            int c0 = j * 8 + cc;
#pragma unroll
            for (int q = 0; q < 4; q++) {
                int col = c0 + (q & 1);
                int rowl = lrow + ((q >> 1) << 3);
                __nv_bfloat16 hb, lb;
                split_bf16(acc[j][q], hb, lb);
                Thi[col * TSTRIDE + rowl] = hb;
                Tlo[col * TSTRIDE + rowl] = lb;
            }
        }
        __syncthreads();
        int col = tid >> 1, half = tid & 1;
        size_t off = ((size_t)bh * DH_ + col) * N_ + mt + half * 32;
        const __nv_bfloat16* shi = Thi + col * TSTRIDE + half * 32;
        const __nv_bfloat16* slo = Tlo + col * TSTRIDE + half * 32;
#pragma unroll
        for (int q = 0; q < 4; q++) {
            *(uint4*)(&g_PThi[wb][off + q * 8]) = *(const uint4*)(shi + q * 8);
            *(uint4*)(&g_PTlo[wb][off + q * 8]) = *(const uint4*)(slo + q * 8);
        }
    }
}

// ---------------------------------------------------------------------------
// Fused filter: H = sum_hop alpha[h,hop] * P[hop] @ W[h,hop]; emits bf16 hi/lo.
// ---------------------------------------------------------------------------
__global__ __launch_bounds__(TPB, 2) void filter_kernel(const float* __restrict__ Wf,
                                                        const float* __restrict__ alpha,
                                                        int bh0) {
    __shared__ float4 As[2][64 * 16], Bs[2][64 * 16];
    int bh = bh0 + blockIdx.y, b = bh >> 3, h = bh & 7;
    int mt = blockIdx.x << 6;
    int tx = threadIdx.x & 15, ty = threadIdx.x >> 4;

    float av[KHOP + 1];
#pragma unroll
    for (int k = 0; k <= KHOP; k++) av[k] = alpha[h * (KHOP + 1) + k];

    float4 ra[4], rb[4];
    ldg_tile(ra, &g_P[0][(size_t)bh * N_ * DH_ + (size_t)mt * DH_], DH_);
    ldg_tile(rb, Wf + (size_t)(h * (KHOP + 1)) * DH_ * DH_, DH_);
#pragma unroll
    for (int i = 0; i < 4; i++) {
        rb[i].x *= av[0]; rb[i].y *= av[0]; rb[i].z *= av[0]; rb[i].w *= av[0];
    }
    sts_tile(As[0], ra);
    sts_tile(Bs[0], rb);
    __syncthreads();

    u64 acc2[4][2];
#pragma unroll
    for (int i = 0; i < 4; i++) { acc2[i][0] = 0ull; acc2[i][1] = 0ull; }

#pragma unroll 1
    for (int hop = 0; hop <= KHOP; hop++) {
        int cur = hop & 1, nxt = cur ^ 1;
        if (hop < KHOP) {
            ldg_tile(ra, &g_P[hop + 1][(size_t)bh * N_ * DH_ + (size_t)mt * DH_], DH_);
            ldg_tile(rb, Wf + (size_t)(h * (KHOP + 1) + hop + 1) * DH_ * DH_, DH_);
            float a1 = av[hop + 1];
#pragma unroll
            for (int i = 0; i < 4; i++) {
                rb[i].x *= a1; rb[i].y *= a1; rb[i].z *= a1; rb[i].w *= a1;
            }
        }
        const float4* Ac = As[cur];
        const u64*   Bc2 = (const u64*)Bs[cur];
#pragma unroll
        for (int k4 = 0; k4 < 16; k4++) {
            float4 a[4];
#pragma unroll
            for (int i = 0; i < 4; i++) a[i] = Ac[(ty * 4 + i) * 16 + (k4 ^ ty)];
#pragma unroll
            for (int c = 0; c < 4; c++) {
                int f = ((k4 * 4 + c) * 16 + (tx ^ k4)) * 2;
                u64 bL = Bc2[f], bH = Bc2[f + 1];
#pragma unroll
                for (int i = 0; i < 4; i++) {
                    u64 s2 = dup2(getc(a[i], c));
                    acc2[i][0] = ffma2(s2, bL, acc2[i][0]);
                    acc2[i][1] = ffma2(s2, bH, acc2[i][1]);
                }
            }
        }
        if (hop < KHOP) {
            sts_tile(As[nxt], ra);
            sts_tile(Bs[nxt], rb);
        }
        __syncthreads();
    }

    size_t base = ((size_t)(b * N_ + mt)) * D_ + h * DH_;
#pragma unroll
    for (int i = 0; i < 4; i++) {
        float2 p0 = unpack2(acc2[i][0]);
        float2 p1 = unpack2(acc2[i][1]);
        uint32_t l01, l23;
        uint32_t h01 = pack_split2(p0.x, p0.y, l01);
        uint32_t h23 = pack_split2(p1.x, p1.y, l23);
        size_t o = base + (size_t)(ty * 4 + i) * D_ + tx * 4;
        *(uint2*)(g_Hhi + o) = make_uint2(h01, h23);
        *(uint2*)(g_Hlo + o) = make_uint2(l01, l23);
    }
}

// ---------------------------------------------------------------------------
// Projection via mma.sync bf16x3: out = H @ W_proj^T + b_proj.
// ---------------------------------------------------------------------------
__device__ __forceinline__ void proj_load_chunk(uint32_t st, int it, int jt, int k0) {
    int t = threadIdx.x;
#pragma unroll
    for (int i = 0; i < 4; i++) {
        int idx = t + i * 128;
        int r = idx >> 3, g = idx & 7;
        uint32_t so = (uint32_t)(r * 128 + ((g ^ (r & 7)) << 4));
        size_t ga = ((size_t)(it + r) * D_ + k0 + g * 8) * 2;
        size_t gb = ((size_t)(jt + r) * D_ + k0 + g * 8) * 2;
        cp16(st + OFF_AHI + so, (const char*)g_Hhi + ga);
        cp16(st + OFF_ALO + so, (const char*)g_Hlo + ga);
        cp16(st + OFF_PHI + so, (const char*)g_Wphi + gb);
        cp16(st + OFF_PLO + so, (const char*)g_Wplo + gb);
    }
}

__global__ __launch_bounds__(128, 3) void proj_mma_kernel(const float* __restrict__ bias,
                                                          float* __restrict__ out) {
    extern __shared__ __align__(1024) char dsm[];
    uint32_t sb = smem_u32(dsm);
    int tid = threadIdx.x, lane = tid & 31, w = tid >> 5;
    int it = blockIdx.y << 6, jt = blockIdx.x << 6;

    int lr = lane & 7, sel = lane >> 3;
    int amrow = (w << 4) + ((sel & 1) << 3) + lr;
    uint32_t aRowOff = (uint32_t)(amrow * 128);
    int aRowX = amrow & 7;
    int aCsel = sel >> 1;
    int bnrow = ((sel >> 1) << 3) + lr;
    int bCsel = sel & 1;

    float acc[8][4];
#pragma unroll
    for (int j = 0; j < 8; j++)
#pragma unroll
        for (int q = 0; q < 4; q++) acc[j][q] = 0.f;

    proj_load_chunk(sb, it, jt, 0);
    CP_COMMIT();

#pragma unroll 1
    for (int kc = 0; kc < 8; kc++) {
        uint32_t cur = (uint32_t)(kc & 1) * STAGE_BYTES;
        if (kc < 7) {
            uint32_t nxt = (uint32_t)((kc + 1) & 1) * STAGE_BYTES;
            proj_load_chunk(sb + nxt, it, jt, (kc + 1) * 64);
            CP_COMMIT();
            CP_WAIT1();
        } else {
            CP_WAIT0();
        }
        __syncthreads();

#pragma unroll
        for (int ks = 0; ks < 4; ks++) {
            uint32_t ahi[4], alo[4];
            {
                int c = 2 * ks + aCsel;
                uint32_t ao = aRowOff + (uint32_t)((c ^ aRowX) << 4);
                ldsm4(ahi, sb + cur + OFF_AHI + ao);
                ldsm4(alo, sb + cur + OFF_ALO + ao);
            }
#pragma unroll
            for (int p = 0; p < 4; p++) {
                int n = (p << 4) + bnrow;
                int c = 2 * ks + bCsel;
                uint32_t bo = (uint32_t)(n * 128 + ((c ^ (n & 7)) << 4));
                uint32_t bhi[4], blo[4];
                ldsm4(bhi, sb + cur + OFF_PHI + bo);
                ldsm4(blo, sb + cur + OFF_PLO + bo);
                mma16816(acc[2 * p],     ahi, bhi[0], bhi[1]);
                mma16816(acc[2 * p],     ahi, blo[0], blo[1]);
                mma16816(acc[2 * p],     alo, bhi[0], bhi[1]);
                mma16816(acc[2 * p + 1], ahi, bhi[2], bhi[3]);
                mma16816(acc[2 * p + 1], ahi, blo[2], blo[3]);
                mma16816(acc[2 * p + 1], alo, bhi[2], bhi[3]);
            }
        }
        __syncthreads();
    }

    int r0 = it + (w << 4) + (lane >> 2);
    int cc = (lane & 3) << 1;
#pragma unroll
    for (int j = 0; j < 8; j++) {
        int col = jt + j * 8 + cc;
        float b0 = bias[col], b1 = bias[col + 1];
        *(float2*)(out + (size_t)r0 * D_ + col) =
            make_float2(acc[j][0] + b0, acc[j][1] + b1);
        *(float2*)(out + (size_t)(r0 + 8) * D_ + col) =
            make_float2(acc[j][2] + b0, acc[j][3] + b1);
    }
}

}  // namespace

extern "C" void kernel_launch(void* const* d_in, const int* in_sizes, int n_in,
                              void* d_out, int out_size) {
    const float* X           = (const float*)d_in[0];
    const float* temperature = (const float*)d_in[1];
    const float* W_filt      = (const float*)d_in[2];
    const float* alpha       = (const float*)d_in[3];
    const float* W_proj      = (const float*)d_in[4];
    const float* b_proj      = (const float*)d_in[5];
    const int*   layer_idx   = (const int*)d_in[6];
    const int*   Lp          = (const int*)d_in[7];
    float* out = (float*)d_out;
    (void)in_sizes; (void)n_in; (void)out_size;

    static cudaStream_t s1, s2;
    static cudaEvent_t ev_pt0, ev_score[NCHUNK], ev_topk[NCHUNK], ev_filt[NCHUNK];
    static bool inited = false;
    if (!inited) {
        cudaFuncSetAttribute(spmm_mma_kernel,
                             cudaFuncAttributeMaxDynamicSharedMemorySize, SMEM_SPMM);
        cudaFuncSetAttribute(proj_mma_kernel,
                             cudaFuncAttributeMaxDynamicSharedMemorySize, SMEM_SPMM);
        cudaStreamCreateWithFlags(&s1, cudaStreamNonBlocking);
        cudaStreamCreateWithFlags(&s2, cudaStreamNonBlocking);
        cudaEventCreateWithFlags(&ev_pt0, cudaEventDisableTiming);
        for (int c = 0; c < NCHUNK; c++) {
            cudaEventCreateWithFlags(&ev_score[c], cudaEventDisableTiming);
            cudaEventCreateWithFlags(&ev_topk[c], cudaEventDisableTiming);
            cudaEventCreateWithFlags(&ev_filt[c], cudaEventDisableTiming);
        }
        inited = true;
    }

    // ---- default stream: pack, wide score chunks, then W split + PT(hop0) ----
    pack_kernel<<<2048, TPB>>>(X);
    for (int c = 0; c < NCHUNK; c++) {
        score_mma_kernel<<<dim3(16, 16, BH_PER_CHUNK), 128>>>(temperature,
                                                              c * BH_PER_CHUNK);
        cudaEventRecord(ev_score[c], 0);
    }
    wp_convert_kernel<<<256, TPB>>>(W_proj);
    pt_convert_kernel<<<dim3(16, 32), 128>>>(0);
    cudaEventRecord(ev_pt0, 0);

    // ---- s1: exact top-k + softmax per wide chunk ----
    for (int c = 0; c < NCHUNK; c++) {
        cudaStreamWaitEvent(s1, ev_score[c], 0);
        topk_softmax_kernel<<<BH_PER_CHUNK * N_ / (TPB / 32), TPB, 0, s1>>>(
            layer_idx, Lp, c * BH_PER_CHUNK * N_);
        cudaEventRecord(ev_topk[c], s1);
    }

    // ---- s2: spmm hop chain (ping-pong PT) + filter per wide chunk ----
    cudaStreamWaitEvent(s2, ev_pt0, 0);
    for (int c = 0; c < NCHUNK; c++) {
        int bh0 = c * BH_PER_CHUNK;
        cudaStreamWaitEvent(s2, ev_topk[c], 0);
        spmm_mma_kernel<<<dim3(16, BH_PER_CHUNK), 128, SMEM_SPMM, s2>>>(1, 1, bh0, 0, 1);
        spmm_mma_kernel<<<dim3(16, BH_PER_CHUNK), 128, SMEM_SPMM, s2>>>(2, 1, bh0, 1, 0);
        spmm_mma_kernel<<<dim3(16, BH_PER_CHUNK), 128, SMEM_SPMM, s2>>>(3, 0, bh0, 0, 0);
        filter_kernel<<<dim3(16, BH_PER_CHUNK), TPB, 0, s2>>>(W_filt, alpha, bh0);
        cudaEventRecord(ev_filt[c], s2);
    }

    // ---- default stream: join all filter chunks, then projection ----
    for (int c = 0; c < NCHUNK; c++)
        cudaStreamWaitEvent(0, ev_filt[c], 0);
    proj_mma_kernel<<<dim3(8, 64), 128, SMEM_SPMM>>>(b_proj, out);
}

// round 16
// speedup vs baseline: 1.0942x; 1.0942x over previous
#include <cuda_runtime.h>
#include <cuda_bf16.h>
#include <math.h>
#include <stdint.h>

#define TPB 256

namespace {

constexpr int B_ = 4, N_ = 1024, D_ = 512, H_ = 8, DH_ = 64, BH_ = 32, KHOP = 3;
constexpr int NCHUNK = 2, BH_PER_CHUNK = BH_ / NCHUNK;   // 16 bh per chunk (wide)

using u64 = unsigned long long;

// Device-global scratch (no allocations allowed)
__device__ float g_S[(size_t)BH_ * N_ * N_];                 // 128 MB fp32 scaled scores
__device__ __nv_bfloat16 g_Ahi[(size_t)BH_ * N_ * N_];       // 64 MB adjacency hi
__device__ __nv_bfloat16 g_Alo[(size_t)BH_ * N_ * N_];       // 64 MB adjacency lo
__device__ __nv_bfloat16 g_Xhi[(size_t)BH_ * N_ * DH_];      // 4 MB  Xh hi (k-major)
__device__ __nv_bfloat16 g_Xlo[(size_t)BH_ * N_ * DH_];      // 4 MB  Xh lo
// Ping-pong P^T buffers: reader and writer of a given spmm launch are disjoint.
__device__ __nv_bfloat16 g_PThi[2][(size_t)BH_ * DH_ * N_];  // 2 x 4 MB
__device__ __nv_bfloat16 g_PTlo[2][(size_t)BH_ * DH_ * N_];  // 2 x 4 MB
__device__ float g_P[KHOP + 1][(size_t)BH_ * N_ * DH_];      // 4 x 8 MB hop buffers
__device__ __nv_bfloat16 g_Hhi[(size_t)B_ * N_ * D_];        // 4 MB filtered out hi
__device__ __nv_bfloat16 g_Hlo[(size_t)B_ * N_ * D_];        // 4 MB filtered out lo
__device__ __nv_bfloat16 g_Wphi[(size_t)D_ * D_];            // 0.5 MB W_proj hi
__device__ __nv_bfloat16 g_Wplo[(size_t)D_ * D_];            // 0.5 MB W_proj lo

// ---------------------------------------------------------------------------
// Packed f32x2 helpers (SIMT filter kernel)
// ---------------------------------------------------------------------------
__device__ __forceinline__ u64 ffma2(u64 a, u64 b, u64 c) {
    u64 d;
    asm("fma.rn.f32x2 %0, %1, %2, %3;" : "=l"(d) : "l"(a), "l"(b), "l"(c));
    return d;
}
__device__ __forceinline__ u64 dup2(float s) {
    u64 d;
    asm("mov.b64 %0, {%1, %1};" : "=l"(d) : "f"(s));
    return d;
}
__device__ __forceinline__ float2 unpack2(u64 v) {
    float2 r;
    asm("mov.b64 {%0, %1}, %2;" : "=f"(r.x), "=f"(r.y) : "l"(v));
    return r;
}

// ---------------------------------------------------------------------------
// cp.async + ldmatrix + mma.sync helpers (valid on compute_103)
// ---------------------------------------------------------------------------
__device__ __forceinline__ uint32_t smem_u32(const void* p) {
    return (uint32_t)__cvta_generic_to_shared(p);
}
__device__ __forceinline__ void cp16(uint32_t s, const void* g) {
    asm volatile("cp.async.cg.shared.global [%0], [%1], 16;" :: "r"(s), "l"(g));
}
#define CP_COMMIT() asm volatile("cp.async.commit_group;" ::: "memory")
#define CP_WAIT1()  asm volatile("cp.async.wait_group 1;" ::: "memory")
#define CP_WAIT0()  asm volatile("cp.async.wait_group 0;" ::: "memory")

__device__ __forceinline__ void ldsm4(uint32_t r[4], uint32_t addr) {
    asm volatile("ldmatrix.sync.aligned.m8n8.x4.shared.b16 {%0,%1,%2,%3}, [%4];"
                 : "=r"(r[0]), "=r"(r[1]), "=r"(r[2]), "=r"(r[3]) : "r"(addr));
}
__device__ __forceinline__ void mma16816(float d[4], const uint32_t a[4],
                                         uint32_t b0, uint32_t b1) {
    asm volatile(
        "mma.sync.aligned.m16n8k16.row.col.f32.bf16.bf16.f32 "
        "{%0,%1,%2,%3}, {%4,%5,%6,%7}, {%8,%9}, {%0,%1,%2,%3};"
        : "+f"(d[0]), "+f"(d[1]), "+f"(d[2]), "+f"(d[3])
        : "r"(a[0]), "r"(a[1]), "r"(a[2]), "r"(a[3]), "r"(b0), "r"(b1));
}

__device__ __forceinline__ void split_bf16(float v, __nv_bfloat16& h, __nv_bfloat16& l) {
    h = __float2bfloat16(v);
    l = __float2bfloat16(v - __bfloat162float(h));
}

__device__ __forceinline__ uint32_t pack_split2(float v0, float v1, uint32_t& lo2) {
    uint32_t hi2;
    asm("cvt.rn.bf16x2.f32 %0, %1, %2;" : "=r"(hi2) : "f"(v1), "f"(v0));
    float h0 = __uint_as_float(hi2 << 16);
    float h1 = __uint_as_float(hi2 & 0xFFFF0000u);
    float l0 = v0 - h0, l1 = v1 - h1;
    asm("cvt.rn.bf16x2.f32 %0, %1, %2;" : "=r"(lo2) : "f"(l1), "f"(l0));
    return hi2;
}

// SMEM layout for mma GEMM kernels: 2 stages x 32KB
constexpr int OFF_AHI = 0;
constexpr int OFF_ALO = 8192;
constexpr int OFF_PHI = 16384;
constexpr int OFF_PLO = 24576;
constexpr int STAGE_BYTES = 32768;
constexpr int SMEM_SPMM = 2 * STAGE_BYTES;   // 64 KB dynamic

// ---------------------------------------------------------------------------
// Tile I/O for SIMT kernels
// ---------------------------------------------------------------------------
__device__ __forceinline__ void ldg_tile(float4 r[4], const float* g, int ldg) {
    int t = threadIdx.x;
#pragma unroll
    for (int i = 0; i < 4; i++) {
        int idx = t + i * TPB;
        int rr = idx >> 4, k4 = idx & 15;
        r[i] = *(const float4*)(g + (size_t)rr * ldg + (k4 << 2));
    }
}
__device__ __forceinline__ void sts_tile(float4* s, const float4 r[4]) {
    int t = threadIdx.x;
#pragma unroll
    for (int i = 0; i < 4; i++) {
        int idx = t + i * TPB;
        int rr = idx >> 4, k4 = idx & 15;
        s[rr * 16 + (k4 ^ (rr >> 2))] = r[i];
    }
}
__device__ __forceinline__ float getc(const float4& v, int c) {
    return c == 0 ? v.x : c == 1 ? v.y : c == 2 ? v.z : v.w;
}

// ---------------------------------------------------------------------------
// Pack Xh: fp32 P[0] + bf16 hi/lo Xh
// ---------------------------------------------------------------------------
__global__ __launch_bounds__(TPB) void pack_kernel(const float* __restrict__ X) {
    int idx = blockIdx.x * TPB + threadIdx.x;
    int d4 = idx & 15;
    int n  = (idx >> 4) & (N_ - 1);
    int bh = idx >> 14;
    int b = bh >> 3, h = bh & 7;
    float4 v = *(const float4*)(X + ((size_t)b * N_ + n) * D_ + h * DH_ + (d4 << 2));
    size_t off = ((size_t)bh * N_ + n) * DH_ + (d4 << 2);
    *(float4*)(&g_P[0][off]) = v;

    uint32_t l01, l23;
    uint32_t h01 = pack_split2(v.x, v.y, l01);
    uint32_t h23 = pack_split2(v.z, v.w, l23);
    *(uint2*)(g_Xhi + off) = make_uint2(h01, h23);
    *(uint2*)(g_Xlo + off) = make_uint2(l01, l23);
}

// ---------------------------------------------------------------------------
// W_proj fp32 [j][d] (k-major) -> bf16 hi/lo
// ---------------------------------------------------------------------------
__global__ __launch_bounds__(TPB) void wp_convert_kernel(const float* __restrict__ Wp) {
    int idx = blockIdx.x * TPB + threadIdx.x;       // 65536 float4 groups
    float4 v = ((const float4*)Wp)[idx];
    uint32_t l01, l23;
    uint32_t h01 = pack_split2(v.x, v.y, l01);
    uint32_t h23 = pack_split2(v.z, v.w, l23);
    *(uint2*)(g_Wphi + (size_t)idx * 4) = make_uint2(h01, h23);
    *(uint2*)(g_Wplo + (size_t)idx * 4) = make_uint2(l01, l23);
}

// ---------------------------------------------------------------------------
// Score via mma.sync bf16x3: S = Xh Xh^T / (8*clip(tau)); 64x64 CTA, K=64.
// ---------------------------------------------------------------------------
__global__ __launch_bounds__(128) void score_mma_kernel(const float* __restrict__ temp,
                                                        int bh0) {
    __shared__ __align__(128) char sa_hi[8192], sa_lo[8192], sb_hi[8192], sb_lo[8192];
    int tid = threadIdx.x, lane = tid & 31, w = tid >> 5;
    int mt = blockIdx.y << 6, nt = blockIdx.x << 6;
    int bh = bh0 + blockIdx.z, h = bh & 7;

    const __nv_bfloat16* Xhi = g_Xhi + (size_t)bh * N_ * DH_;
    const __nv_bfloat16* Xlo = g_Xlo + (size_t)bh * N_ * DH_;

    {
        uint32_t ah = smem_u32(sa_hi), al = smem_u32(sa_lo);
        uint32_t bhp = smem_u32(sb_hi), blp = smem_u32(sb_lo);
#pragma unroll
        for (int i = 0; i < 4; i++) {
            int idx = tid + i * 128;
            int r = idx >> 3, g = idx & 7;
            uint32_t so = (uint32_t)(r * 128 + ((g ^ (r & 7)) << 4));
            size_t ga = ((size_t)(mt + r) * DH_ + g * 8) * 2;
            size_t gb = ((size_t)(nt + r) * DH_ + g * 8) * 2;
            cp16(ah + so, (const char*)Xhi + ga);
            cp16(al + so, (const char*)Xlo + ga);
            cp16(bhp + so, (const char*)Xhi + gb);
            cp16(blp + so, (const char*)Xlo + gb);
        }
    }
    CP_COMMIT();
    CP_WAIT0();
    __syncthreads();

    int lr = lane & 7, sel = lane >> 3;
    int amrow = (w << 4) + ((sel & 1) << 3) + lr;
    uint32_t aRowOff = (uint32_t)(amrow * 128);
    int aRowX = amrow & 7;
    int aCsel = sel >> 1;
    int bnrow = ((sel >> 1) << 3) + lr;
    int bCsel = sel & 1;

    float acc[8][4];
#pragma unroll
    for (int j = 0; j < 8; j++)
#pragma unroll
        for (int q = 0; q < 4; q++) acc[j][q] = 0.f;

    uint32_t sah = smem_u32(sa_hi), sal = smem_u32(sa_lo);
    uint32_t sbh = smem_u32(sb_hi), sbl = smem_u32(sb_lo);
#pragma unroll
    for (int ks = 0; ks < 4; ks++) {
        uint32_t ahi[4], alo[4];
        {
            int c = 2 * ks + aCsel;
            uint32_t ao = aRowOff + (uint32_t)((c ^ aRowX) << 4);
            ldsm4(ahi, sah + ao);
            ldsm4(alo, sal + ao);
        }
#pragma unroll
        for (int p = 0; p < 4; p++) {
            int n = (p << 4) + bnrow;
            int c = 2 * ks + bCsel;
            uint32_t bo = (uint32_t)(n * 128 + ((c ^ (n & 7)) << 4));
            uint32_t bhi[4], blo[4];
            ldsm4(bhi, sbh + bo);
            ldsm4(blo, sbl + bo);
            mma16816(acc[2 * p],     ahi, bhi[0], bhi[1]);
            mma16816(acc[2 * p],     ahi, blo[0], blo[1]);
            mma16816(acc[2 * p],     alo, bhi[0], bhi[1]);
            mma16816(acc[2 * p + 1], ahi, bhi[2], bhi[3]);
            mma16816(acc[2 * p + 1], ahi, blo[2], blo[3]);
            mma16816(acc[2 * p + 1], alo, bhi[2], bhi[3]);
        }
    }

    float tau = fminf(fmaxf(temp[h], 0.1f), 5.0f);
    float sc = 1.0f / (8.0f * tau);

    float* Sb = g_S + (size_t)bh * N_ * N_;
    int r0 = mt + (w << 4) + (lane >> 2);
    int cc = nt + ((lane & 3) << 1);
#pragma unroll
    for (int j = 0; j < 8; j++) {
        *(float2*)(Sb + (size_t)r0 * N_ + j * 8 + cc) =
            make_float2(acc[j][0] * sc, acc[j][1] * sc);
        *(float2*)(Sb + (size_t)(r0 + 8) * N_ + j * 8 + cc) =
            make_float2(acc[j][2] * sc, acc[j][3] * sc);
    }
}

// ---------------------------------------------------------------------------
// Exact top-k threshold + softmax, warp-per-row; emits bf16 hi/lo adjacency.
// Early-exit: if count(key >= cand) == k exactly, {key >= cand} IS the top-k
// set, so masking with cand<<16 keeps the identical element set (all excluded
// keys < cand <= kth-largest) -> output bit-identical, phase-2 skipped.
// ---------------------------------------------------------------------------
__global__ __launch_bounds__(TPB) void topk_softmax_kernel(const int* __restrict__ layer_idx,
                                                           const int* __restrict__ Lp,
                                                           int row0) {
    int lane = threadIdx.x & 31;
    size_t row = (size_t)row0 + (size_t)blockIdx.x * (TPB / 32) + (threadIdx.x >> 5);
    const float4* s4 = (const float4*)(g_S + row * N_);

    float4 d4v[8];
#pragma unroll
    for (int i = 0; i < 8; i++) d4v[i] = s4[lane + i * 32];

    unsigned uu[32];
#pragma unroll
    for (int i = 0; i < 8; i++) {
        const float* f = (const float*)&d4v[i];
#pragma unroll
        for (int j = 0; j < 4; j++) {
            unsigned bits = __float_as_uint(f[j]);
            uu[i * 4 + j] = (bits & 0x80000000u) ? ~bits : (bits | 0x80000000u);
        }
    }

    int li = layer_idx[0], Lv = Lp[0];
    double sp = 0.8 + (0.2 - 0.8) * exp(-3.0 * (double)li / (double)Lv);
    int k_val = (int)((1.0 - sp) * (double)N_);
    if (k_val < 1) k_val = 1;
    bool do_thresh = (k_val < N_);

    unsigned T = 0u;
    if (do_thresh) {
        unsigned hi[32];
#pragma unroll
        for (int i = 0; i < 32; i++) hi[i] = uu[i] >> 16;

        unsigned P = 0u;
        bool exact = false;
#pragma unroll 1
        for (int b = 15; b >= 0; --b) {
            unsigned cand = P | (1u << b);
            int c = 0;
#pragma unroll
            for (int i = 0; i < 32; i++) c += (hi[i] >= cand) ? 1 : 0;
            c = __reduce_add_sync(0xFFFFFFFFu, c);
            if (c >= k_val) {
                P = cand;
                if (c == k_val) { exact = true; break; }
            }
        }

        if (exact) {
            T = P << 16;
        } else {
            int cgt = 0;
#pragma unroll
            for (int i = 0; i < 32; i++) cgt += (hi[i] > P) ? 1 : 0;
            cgt = __reduce_add_sync(0xFFFFFFFFu, cgt);
            int j = k_val - cgt;

            unsigned act = 0u;
            unsigned lo[32];
#pragma unroll
            for (int i = 0; i < 32; i++) {
                lo[i] = uu[i] & 0xFFFFu;
                if (hi[i] == P) act |= (1u << i);
            }
            unsigned Mfin = 0u;
#pragma unroll 1
            while (true) {
                unsigned m = 0u;
#pragma unroll
                for (int i = 0; i < 32; i++)
                    if (act & (1u << i)) m = m > lo[i] ? m : lo[i];
                m = __reduce_max_sync(0xFFFFFFFFu, m);
                int q = 0;
                unsigned hitm = 0u;
#pragma unroll
                for (int i = 0; i < 32; i++)
                    if ((act & (1u << i)) && lo[i] == m) { q++; hitm |= (1u << i); }
                q = __reduce_add_sync(0xFFFFFFFFu, q);
                if (j <= q) { Mfin = m; break; }
                j -= q;
                act &= ~hitm;
            }
            T = (P << 16) | Mfin;
        }
    }

    float v[32];
    float vmax = -INFINITY;
#pragma unroll
    for (int i = 0; i < 32; i++) {
        unsigned u = uu[i];
        unsigned bits = (u & 0x80000000u) ? (u ^ 0x80000000u) : ~u;
        v[i] = __uint_as_float(bits);
        vmax = fmaxf(vmax, v[i]);
    }
#pragma unroll
    for (int o = 16; o > 0; o >>= 1)
        vmax = fmaxf(vmax, __shfl_xor_sync(0xFFFFFFFFu, vmax, o));

    float ssum = 0.f;
#pragma unroll
    for (int i = 0; i < 32; i++) {
        bool keep = (!do_thresh) || (uu[i] >= T);
        float ev = keep ? expf(v[i] - vmax) : 0.f;
        v[i] = ev;
        ssum += ev;
    }
#pragma unroll
    for (int o = 16; o > 0; o >>= 1)
        ssum += __shfl_xor_sync(0xFFFFFFFFu, ssum, o);
    float inv = 1.0f / ssum;

    __nv_bfloat16* ahrow = g_Ahi + row * N_;
    __nv_bfloat16* alrow = g_Alo + row * N_;
#pragma unroll
    for (int i = 0; i < 8; i++) {
        __nv_bfloat16 hh[4], ll[4];
#pragma unroll
        for (int j = 0; j < 4; j++) split_bf16(v[i * 4 + j] * inv, hh[j], ll[j]);
        *(uint2*)(ahrow + (lane + i * 32) * 4) = *(const uint2*)hh;
        *(uint2*)(alrow + (lane + i * 32) * 4) = *(const uint2*)ll;
    }
}

// ---------------------------------------------------------------------------
// PT convert (hop 0 only): P[0] fp32 -> PT buffer 0 bf16 hi/lo [bh][n][k]
// ---------------------------------------------------------------------------
__global__ __launch_bounds__(128) void pt_convert_kernel(int hop) {
    __shared__ float tile[64][65];
    int kt = blockIdx.x, bh = blockIdx.y;
    const float* src = &g_P[hop][(size_t)bh * N_ * DH_ + (size_t)kt * 64 * DH_];
    int t = threadIdx.x;
#pragma unroll
    for (int i = 0; i < 8; i++) {
        int idx = t + i * 128;
        int r = idx >> 4, c4 = idx & 15;
        float4 v = *(const float4*)(src + (size_t)r * DH_ + c4 * 4);
        tile[r][c4 * 4 + 0] = v.x;
        tile[r][c4 * 4 + 1] = v.y;
        tile[r][c4 * 4 + 2] = v.z;
        tile[r][c4 * 4 + 3] = v.w;
    }
    __syncthreads();
    int n = t >> 1, kh = (t & 1) * 32;
    __nv_bfloat16 hi[32], lo[32];
#pragma unroll
    for (int k = 0; k < 32; k++) split_bf16(tile[kh + k][n], hi[k], lo[k]);
    size_t off = ((size_t)bh * DH_ + n) * N_ + kt * 64 + kh;
#pragma unroll
    for (int q = 0; q < 4; q++) {
        *(uint4*)(&g_PThi[0][off + q * 8]) = *(const uint4*)(hi + q * 8);
        *(uint4*)(&g_PTlo[0][off + q * 8]) = *(const uint4*)(lo + q * 8);
    }
}

// ---------------------------------------------------------------------------
// spmm via mma.sync bf16x3:  P[hop] = A @ P[hop-1].
// Reads PT[rb], optionally writes transposed PT[wb] (rb != wb: race-free).
// ---------------------------------------------------------------------------
__device__ __forceinline__ void spmm_load_chunk(
    uint32_t st, const __nv_bfloat16* Ahi, const __nv_bfloat16* Alo,
    const __nv_bfloat16* Phi, const __nv_bfloat16* Plo, int mt, int k0)
{
    int t = threadIdx.x;
#pragma unroll
    for (int i = 0; i < 4; i++) {
        int idx = t + i * 128;
        int r = idx >> 3, g = idx & 7;
        uint32_t so = (uint32_t)(r * 128 + ((g ^ (r & 7)) << 4));
        size_t go = ((size_t)(mt + r) * N_ + k0 + g * 8) * 2;
        cp16(st + OFF_AHI + so, (const char*)Ahi + go);
        cp16(st + OFF_ALO + so, (const char*)Alo + go);
        size_t gp = ((size_t)r * N_ + k0 + g * 8) * 2;
        cp16(st + OFF_PHI + so, (const char*)Phi + gp);
        cp16(st + OFF_PLO + so, (const char*)Plo + gp);
    }
}

constexpr int TSTRIDE = 72;   // bf16 elements; pads banks for transposed readout

__global__ __launch_bounds__(128, 2) void spmm_mma_kernel(int hop, int want_pt,
                                                          int bh0, int rb, int wb) {
    extern __shared__ __align__(1024) char dsm[];
    uint32_t sb = smem_u32(dsm);
    int tid = threadIdx.x, lane = tid & 31, w = tid >> 5;
    int mt = blockIdx.x << 6;
    int bh = bh0 + blockIdx.y;

    const __nv_bfloat16* Ahi = g_Ahi + (size_t)bh * N_ * N_;
    const __nv_bfloat16* Alo = g_Alo + (size_t)bh * N_ * N_;
    const __nv_bfloat16* Phi = &g_PThi[rb][(size_t)bh * DH_ * N_];
    const __nv_bfloat16* Plo = &g_PTlo[rb][(size_t)bh * DH_ * N_];
    float* Pout = &g_P[hop][(size_t)bh * N_ * DH_];

    int lr = lane & 7, sel = lane >> 3;
    int amrow = (w << 4) + ((sel & 1) << 3) + lr;
    uint32_t aRowOff = (uint32_t)(amrow * 128);
    int aRowX = amrow & 7;
    int aCsel = sel >> 1;
    int bnrow = ((sel >> 1) << 3) + lr;
    int bCsel = sel & 1;

    float acc[8][4];
#pragma unroll
    for (int j = 0; j < 8; j++)
#pragma unroll
        for (int q = 0; q < 4; q++) acc[j][q] = 0.f;

    spmm_load_chunk(sb, Ahi, Alo, Phi, Plo, mt, 0);
    CP_COMMIT();

#pragma unroll 1
    for (int kc = 0; kc < 16; kc++) {
        uint32_t cur = (uint32_t)(kc & 1) * STAGE_BYTES;
        if (kc < 15) {
            uint32_t nxt = (uint32_t)((kc + 1) & 1) * STAGE_BYTES;
            spmm_load_chunk(sb + nxt, Ahi, Alo, Phi, Plo, mt, (kc + 1) * 64);
            CP_COMMIT();
            CP_WAIT1();
        } else {
            CP_WAIT0();
        }
        __syncthreads();

#pragma unroll
        for (int ks = 0; ks < 4; ks++) {
            uint32_t ahi[4], alo[4];
            {
                int c = 2 * ks + aCsel;
                uint32_t ao = aRowOff + (uint32_t)((c ^ aRowX) << 4);
                ldsm4(ahi, sb + cur + OFF_AHI + ao);
                ldsm4(alo, sb + cur + OFF_ALO + ao);
            }
#pragma unroll
            for (int p = 0; p < 4; p++) {
                int n = (p << 4) + bnrow;
                int c = 2 * ks + bCsel;
                uint32_t bo = (uint32_t)(n * 128 + ((c ^ (n & 7)) << 4));
                uint32_t bhi[4], blo[4];
                ldsm4(bhi, sb + cur + OFF_PHI + bo);
                ldsm4(blo, sb + cur + OFF_PLO + bo);
                mma16816(acc[2 * p],     ahi, bhi[0], bhi[1]);
                mma16816(acc[2 * p],     ahi, blo[0], blo[1]);
                mma16816(acc[2 * p],     alo, bhi[0], bhi[1]);
                mma16816(acc[2 * p + 1], ahi, bhi[2], bhi[3]);
                mma16816(acc[2 * p + 1], ahi, blo[2], blo[3]);
                mma16816(acc[2 * p + 1], alo, bhi[2], bhi[3]);
            }
        }
        __syncthreads();
    }

    // fp32 P output
    int lrow = (w << 4) + (lane >> 2);       // local row 0..63
    int r0 = mt + lrow;
    int cc = (lane & 3) << 1;
#pragma unroll
    for (int j = 0; j < 8; j++) {
        *(float2*)(Pout + (size_t)r0 * DH_ + j * 8 + cc) =
            make_float2(acc[j][0], acc[j][1]);
        *(float2*)(Pout + (size_t)(r0 + 8) * DH_ + j * 8 + cc) =
            make_float2(acc[j][2], acc[j][3]);
    }

    // Fused transposed bf16 hi/lo PT output into the OTHER buffer (wb != rb)
    if (want_pt) {
        __nv_bfloat16* Thi = (__nv_bfloat16*)dsm;
        __nv_bfloat16* Tlo = (__nv_bfloat16*)(dsm + 64 * TSTRIDE * 2);
#pragma unroll
        for (int j = 0; j < 8; j++) {
            int c0 = j * 8 + cc;
#pragma unroll
            for (int q = 0; q < 4; q++) {
                int col = c0 + (q & 1);
                int rowl = lrow + ((q >> 1) << 3);
                __nv_bfloat16 hb, lb;
                split_bf16(acc[j][q], hb, lb);
                Thi[col * TSTRIDE + rowl] = hb;
                Tlo[col * TSTRIDE + rowl] = lb;
            }
        }
        __syncthreads();
        int col = tid >> 1, half = tid & 1;
        size_t off = ((size_t)bh * DH_ + col) * N_ + mt + half * 32;
        const __nv_bfloat16* shi = Thi + col * TSTRIDE + half * 32;
        const __nv_bfloat16* slo = Tlo + col * TSTRIDE + half * 32;
#pragma unroll
        for (int q = 0; q < 4; q++) {
            *(uint4*)(&g_PThi[wb][off + q * 8]) = *(const uint4*)(shi + q * 8);
            *(uint4*)(&g_PTlo[wb][off + q * 8]) = *(const uint4*)(slo + q * 8);
        }
    }
}

// ---------------------------------------------------------------------------
// Fused filter: H = sum_hop alpha[h,hop] * P[hop] @ W[h,hop]; emits bf16 hi/lo.
// ---------------------------------------------------------------------------
__global__ __launch_bounds__(TPB, 2) void filter_kernel(const float* __restrict__ Wf,
                                                        const float* __restrict__ alpha,
                                                        int bh0) {
    __shared__ float4 As[2][64 * 16], Bs[2][64 * 16];
    int bh = bh0 + blockIdx.y, b = bh >> 3, h = bh & 7;
    int mt = blockIdx.x << 6;
    int tx = threadIdx.x & 15, ty = threadIdx.x >> 4;

    float av[KHOP + 1];
#pragma unroll
    for (int k = 0; k <= KHOP; k++) av[k] = alpha[h * (KHOP + 1) + k];

    float4 ra[4], rb[4];
    ldg_tile(ra, &g_P[0][(size_t)bh * N_ * DH_ + (size_t)mt * DH_], DH_);
    ldg_tile(rb, Wf + (size_t)(h * (KHOP + 1)) * DH_ * DH_, DH_);
#pragma unroll
    for (int i = 0; i < 4; i++) {
        rb[i].x *= av[0]; rb[i].y *= av[0]; rb[i].z *= av[0]; rb[i].w *= av[0];
    }
    sts_tile(As[0], ra);
    sts_tile(Bs[0], rb);
    __syncthreads();

    u64 acc2[4][2];
#pragma unroll
    for (int i = 0; i < 4; i++) { acc2[i][0] = 0ull; acc2[i][1] = 0ull; }

#pragma unroll 1
    for (int hop = 0; hop <= KHOP; hop++) {
        int cur = hop & 1, nxt = cur ^ 1;
        if (hop < KHOP) {
            ldg_tile(ra, &g_P[hop + 1][(size_t)bh * N_ * DH_ + (size_t)mt * DH_], DH_);
            ldg_tile(rb, Wf + (size_t)(h * (KHOP + 1) + hop + 1) * DH_ * DH_, DH_);
            float a1 = av[hop + 1];
#pragma unroll
            for (int i = 0; i < 4; i++) {
                rb[i].x *= a1; rb[i].y *= a1; rb[i].z *= a1; rb[i].w *= a1;
            }
        }
        const float4* Ac = As[cur];
        const u64*   Bc2 = (const u64*)Bs[cur];
#pragma unroll
        for (int k4 = 0; k4 < 16; k4++) {
            float4 a[4];
#pragma unroll
            for (int i = 0; i < 4; i++) a[i] = Ac[(ty * 4 + i) * 16 + (k4 ^ ty)];
#pragma unroll
            for (int c = 0; c < 4; c++) {
                int f = ((k4 * 4 + c) * 16 + (tx ^ k4)) * 2;
                u64 bL = Bc2[f], bH = Bc2[f + 1];
#pragma unroll
                for (int i = 0; i < 4; i++) {
                    u64 s2 = dup2(getc(a[i], c));
                    acc2[i][0] = ffma2(s2, bL, acc2[i][0]);
                    acc2[i][1] = ffma2(s2, bH, acc2[i][1]);
                }
            }
        }
        if (hop < KHOP) {
            sts_tile(As[nxt], ra);
            sts_tile(Bs[nxt], rb);
        }
        __syncthreads();
    }

    size_t base = ((size_t)(b * N_ + mt)) * D_ + h * DH_;
#pragma unroll
    for (int i = 0; i < 4; i++) {
        float2 p0 = unpack2(acc2[i][0]);
        float2 p1 = unpack2(acc2[i][1]);
        uint32_t l01, l23;
        uint32_t h01 = pack_split2(p0.x, p0.y, l01);
        uint32_t h23 = pack_split2(p1.x, p1.y, l23);
        size_t o = base + (size_t)(ty * 4 + i) * D_ + tx * 4;
        *(uint2*)(g_Hhi + o) = make_uint2(h01, h23);
        *(uint2*)(g_Hlo + o) = make_uint2(l01, l23);
    }
}

// ---------------------------------------------------------------------------
// Projection via mma.sync bf16x3: out = H @ W_proj^T + b_proj.
// ---------------------------------------------------------------------------
__device__ __forceinline__ void proj_load_chunk(uint32_t st, int it, int jt, int k0) {
    int t = threadIdx.x;
#pragma unroll
    for (int i = 0; i < 4; i++) {
        int idx = t + i * 128;
        int r = idx >> 3, g = idx & 7;
        uint32_t so = (uint32_t)(r * 128 + ((g ^ (r & 7)) << 4));
        size_t ga = ((size_t)(it + r) * D_ + k0 + g * 8) * 2;
        size_t gb = ((size_t)(jt + r) * D_ + k0 + g * 8) * 2;
        cp16(st + OFF_AHI + so, (const char*)g_Hhi + ga);
        cp16(st + OFF_ALO + so, (const char*)g_Hlo + ga);
        cp16(st + OFF_PHI + so, (const char*)g_Wphi + gb);
        cp16(st + OFF_PLO + so, (const char*)g_Wplo + gb);
    }
}

__global__ __launch_bounds__(128, 2) void proj_mma_kernel(const float* __restrict__ bias,
                                                          float* __restrict__ out) {
    extern __shared__ __align__(1024) char dsm[];
    uint32_t sb = smem_u32(dsm);
    int tid = threadIdx.x, lane = tid & 31, w = tid >> 5;
    int it = blockIdx.y << 6, jt = blockIdx.x << 6;

    int lr = lane & 7, sel = lane >> 3;
    int amrow = (w << 4) + ((sel & 1) << 3) + lr;
    uint32_t aRowOff = (uint32_t)(amrow * 128);
    int aRowX = amrow & 7;
    int aCsel = sel >> 1;
    int bnrow = ((sel >> 1) << 3) + lr;
    int bCsel = sel & 1;

    float acc[8][4];
#pragma unroll
    for (int j = 0; j < 8; j++)
#pragma unroll
        for (int q = 0; q < 4; q++) acc[j][q] = 0.f;

    proj_load_chunk(sb, it, jt, 0);
    CP_COMMIT();

#pragma unroll 1
    for (int kc = 0; kc < 8; kc++) {
        uint32_t cur = (uint32_t)(kc & 1) * STAGE_BYTES;
        if (kc < 7) {
            uint32_t nxt = (uint32_t)((kc + 1) & 1) * STAGE_BYTES;
            proj_load_chunk(sb + nxt, it, jt, (kc + 1) * 64);
            CP_COMMIT();
            CP_WAIT1();
        } else {
            CP_WAIT0();
        }
        __syncthreads();

#pragma unroll
        for (int ks = 0; ks < 4; ks++) {
            uint32_t ahi[4], alo[4];
            {
                int c = 2 * ks + aCsel;
                uint32_t ao = aRowOff + (uint32_t)((c ^ aRowX) << 4);
                ldsm4(ahi, sb + cur + OFF_AHI + ao);
                ldsm4(alo, sb + cur + OFF_ALO + ao);
            }
#pragma unroll
            for (int p = 0; p < 4; p++) {
                int n = (p << 4) + bnrow;
                int c = 2 * ks + bCsel;
                uint32_t bo = (uint32_t)(n * 128 + ((c ^ (n & 7)) << 4));
                uint32_t bhi[4], blo[4];
                ldsm4(bhi, sb + cur + OFF_PHI + bo);
                ldsm4(blo, sb + cur + OFF_PLO + bo);
                mma16816(acc[2 * p],     ahi, bhi[0], bhi[1]);
                mma16816(acc[2 * p],     ahi, blo[0], blo[1]);
                mma16816(acc[2 * p],     alo, bhi[0], bhi[1]);
                mma16816(acc[2 * p + 1], ahi, bhi[2], bhi[3]);
                mma16816(acc[2 * p + 1], ahi, blo[2], blo[3]);
                mma16816(acc[2 * p + 1], alo, bhi[2], bhi[3]);
            }
        }
        __syncthreads();
    }

    int r0 = it + (w << 4) + (lane >> 2);
    int cc = (lane & 3) << 1;
#pragma unroll
    for (int j = 0; j < 8; j++) {
        int col = jt + j * 8 + cc;
        float b0 = bias[col], b1 = bias[col + 1];
        *(float2*)(out + (size_t)r0 * D_ + col) =
            make_float2(acc[j][0] + b0, acc[j][1] + b1);
        *(float2*)(out + (size_t)(r0 + 8) * D_ + col) =
            make_float2(acc[j][2] + b0, acc[j][3] + b1);
    }
}

}  // namespace

extern "C" void kernel_launch(void* const* d_in, const int* in_sizes, int n_in,
                              void* d_out, int out_size) {
    const float* X           = (const float*)d_in[0];
    const float* temperature = (const float*)d_in[1];
    const float* W_filt      = (const float*)d_in[2];
    const float* alpha       = (const float*)d_in[3];
    const float* W_proj      = (const float*)d_in[4];
    const float* b_proj      = (const float*)d_in[5];
    const int*   layer_idx   = (const int*)d_in[6];
    const int*   Lp          = (const int*)d_in[7];
    float* out = (float*)d_out;
    (void)in_sizes; (void)n_in; (void)out_size;

    static cudaStream_t s1, s2;
    static cudaEvent_t ev_pt0, ev_score[NCHUNK], ev_topk[NCHUNK], ev_filt[NCHUNK];
    static bool inited = false;
    if (!inited) {
        cudaFuncSetAttribute(spmm_mma_kernel,
                             cudaFuncAttributeMaxDynamicSharedMemorySize, SMEM_SPMM);
        cudaFuncSetAttribute(proj_mma_kernel,
                             cudaFuncAttributeMaxDynamicSharedMemorySize, SMEM_SPMM);
        cudaStreamCreateWithFlags(&s1, cudaStreamNonBlocking);
        cudaStreamCreateWithFlags(&s2, cudaStreamNonBlocking);
        cudaEventCreateWithFlags(&ev_pt0, cudaEventDisableTiming);
        for (int c = 0; c < NCHUNK; c++) {
            cudaEventCreateWithFlags(&ev_score[c], cudaEventDisableTiming);
            cudaEventCreateWithFlags(&ev_topk[c], cudaEventDisableTiming);
            cudaEventCreateWithFlags(&ev_filt[c], cudaEventDisableTiming);
        }
        inited = true;
    }

    // ---- default stream: pack, wide score chunks, then W split + PT(hop0) ----
    pack_kernel<<<2048, TPB>>>(X);
    for (int c = 0; c < NCHUNK; c++) {
        score_mma_kernel<<<dim3(16, 16, BH_PER_CHUNK), 128>>>(temperature,
                                                              c * BH_PER_CHUNK);
        cudaEventRecord(ev_score[c], 0);
    }
    wp_convert_kernel<<<256, TPB>>>(W_proj);
    pt_convert_kernel<<<dim3(16, 32), 128>>>(0);
    cudaEventRecord(ev_pt0, 0);

    // ---- s1: exact top-k + softmax per wide chunk ----
    for (int c = 0; c < NCHUNK; c++) {
        cudaStreamWaitEvent(s1, ev_score[c], 0);
        topk_softmax_kernel<<<BH_PER_CHUNK * N_ / (TPB / 32), TPB, 0, s1>>>(
            layer_idx, Lp, c * BH_PER_CHUNK * N_);
        cudaEventRecord(ev_topk[c], s1);
    }

    // ---- s2: spmm hop chain (ping-pong PT) + filter per wide chunk ----
    cudaStreamWaitEvent(s2, ev_pt0, 0);
    for (int c = 0; c < NCHUNK; c++) {
        int bh0 = c * BH_PER_CHUNK;
        cudaStreamWaitEvent(s2, ev_topk[c], 0);
        spmm_mma_kernel<<<dim3(16, BH_PER_CHUNK), 128, SMEM_SPMM, s2>>>(1, 1, bh0, 0, 1);
        spmm_mma_kernel<<<dim3(16, BH_PER_CHUNK), 128, SMEM_SPMM, s2>>>(2, 1, bh0, 1, 0);
        spmm_mma_kernel<<<dim3(16, BH_PER_CHUNK), 128, SMEM_SPMM, s2>>>(3, 0, bh0, 0, 0);
        filter_kernel<<<dim3(16, BH_PER_CHUNK), TPB, 0, s2>>>(W_filt, alpha, bh0);
        cudaEventRecord(ev_filt[c], s2);
    }

    // ---- default stream: join all filter chunks, then projection ----
    for (int c = 0; c < NCHUNK; c++)
        cudaStreamWaitEvent(0, ev_filt[c], 0);
    proj_mma_kernel<<<dim3(8, 64), 128, SMEM_SPMM>>>(b_proj, out);
}